// round 4
// baseline (speedup 1.0000x reference)
#include <cuda_runtime.h>
#include <math.h>

#define NPTS 8192
#define DIM  128

// ---------------- device scratch (no allocations allowed) ----------------
__device__ float         g_dist[(size_t)NPTS * NPTS];  // 256 MB distance matrix
__device__ float         g_sq[NPTS];
__device__ unsigned char g_lab[NPTS];
__device__ float         g_loss[NPTS];
__device__ float         g_accv[NPTS];
__device__ float         g_tpv[NPTS];
__device__ float         g_tnv[NPTS];
__device__ int           g_is32;

// ---------------- dtype detection for targets (int32 vs int64) -----------
// Labels are uniform in [0,128). If targets are int64 little-endian, every odd
// int32 slot (high word) is 0. If int32, odd slots are real labels and the OR
// over 4096 of them is nonzero with overwhelming certainty. Only reads the
// first 8192 int32 slots = 32KB, safe for either layout.
__global__ void detect_kernel(const int* __restrict__ t) {
    int local = 0;
    for (int j = threadIdx.x; j < 4096; j += blockDim.x) local |= t[2 * j + 1];
#pragma unroll
    for (int off = 16; off; off >>= 1) local |= __shfl_down_sync(0xffffffffu, local, off);
    __shared__ int s[8];
    if ((threadIdx.x & 31) == 0) s[threadIdx.x >> 5] = local;
    __syncthreads();
    if (threadIdx.x == 0) {
        int f = 0;
        for (int w = 0; w < 8; w++) f |= s[w];
        g_is32 = (f != 0);
    }
}

__global__ void conv_kernel(const void* __restrict__ t) {
    int is32 = g_is32;
    int i = blockIdx.x * blockDim.x + threadIdx.x;
    if (i < NPTS) {
        int v = is32 ? ((const int*)t)[i] : (int)(((const long long*)t)[i]);
        g_lab[i] = (unsigned char)v;
    }
}

// ---------------- squared norms ----------------
__global__ void sq_kernel(const float* __restrict__ X) {
    int i = blockIdx.x;
    int tid = threadIdx.x;  // 128 threads
    float v = X[i * DIM + tid];
    v *= v;
#pragma unroll
    for (int off = 16; off; off >>= 1) v += __shfl_down_sync(0xffffffffu, v, off);
    __shared__ float s[4];
    if ((tid & 31) == 0) s[tid >> 5] = v;
    __syncthreads();
    if (tid == 0) g_sq[i] = s[0] + s[1] + s[2] + s[3];
}

// ---------------- distance matrix: tiled fp32 "GEMM" ----------------
// 128x128 tile per block, 256 threads, 8x8 micro-tile per thread, BK=16.
__global__ void __launch_bounds__(256) dist_kernel(const float* __restrict__ X) {
    __shared__ float As[16][128];
    __shared__ float Bs[16][128];

    const int bx = blockIdx.x;  // column tile (j)
    const int by = blockIdx.y;  // row tile (i)
    const int tid = threadIdx.x;
    const int tx = tid & 15;
    const int ty = tid >> 4;
    const int rowbase = by * 128;
    const int colbase = bx * 128;

    float acc[8][8];
#pragma unroll
    for (int a = 0; a < 8; a++)
#pragma unroll
        for (int b = 0; b < 8; b++) acc[a][b] = 0.0f;

    for (int k0 = 0; k0 < DIM; k0 += 16) {
#pragma unroll
        for (int r = 0; r < 2; r++) {
            int pos = tid + r * 256;     // 0..511
            int row = pos >> 2;          // 0..127
            int kc  = pos & 3;           // 0..3 (float4 chunk within the 16 k's)
            float4 va = *(const float4*)&X[(size_t)(rowbase + row) * DIM + k0 + kc * 4];
            As[kc * 4 + 0][row] = va.x;
            As[kc * 4 + 1][row] = va.y;
            As[kc * 4 + 2][row] = va.z;
            As[kc * 4 + 3][row] = va.w;
            float4 vb = *(const float4*)&X[(size_t)(colbase + row) * DIM + k0 + kc * 4];
            Bs[kc * 4 + 0][row] = vb.x;
            Bs[kc * 4 + 1][row] = vb.y;
            Bs[kc * 4 + 2][row] = vb.z;
            Bs[kc * 4 + 3][row] = vb.w;
        }
        __syncthreads();
#pragma unroll
        for (int kk = 0; kk < 16; kk++) {
            float ar[8], br[8];
            *(float4*)&ar[0] = *(const float4*)&As[kk][ty * 8];
            *(float4*)&ar[4] = *(const float4*)&As[kk][ty * 8 + 4];
            *(float4*)&br[0] = *(const float4*)&Bs[kk][tx * 8];
            *(float4*)&br[4] = *(const float4*)&Bs[kk][tx * 8 + 4];
#pragma unroll
            for (int a = 0; a < 8; a++)
#pragma unroll
                for (int b = 0; b < 8; b++) acc[a][b] = fmaf(ar[a], br[b], acc[a][b]);
        }
        __syncthreads();
    }

    float sqa[8], sqb[8];
#pragma unroll
    for (int a = 0; a < 8; a++) sqa[a] = g_sq[rowbase + ty * 8 + a];
#pragma unroll
    for (int b = 0; b < 8; b++) sqb[b] = g_sq[colbase + tx * 8 + b];

#pragma unroll
    for (int a = 0; a < 8; a++) {
        int row = rowbase + ty * 8 + a;
        float4 o0, o1;
        o0.x = sqrtf(fmaxf(sqa[a] + sqb[0] - 2.0f * acc[a][0], 1e-12f));
        o0.y = sqrtf(fmaxf(sqa[a] + sqb[1] - 2.0f * acc[a][1], 1e-12f));
        o0.z = sqrtf(fmaxf(sqa[a] + sqb[2] - 2.0f * acc[a][2], 1e-12f));
        o0.w = sqrtf(fmaxf(sqa[a] + sqb[3] - 2.0f * acc[a][3], 1e-12f));
        o1.x = sqrtf(fmaxf(sqa[a] + sqb[4] - 2.0f * acc[a][4], 1e-12f));
        o1.y = sqrtf(fmaxf(sqa[a] + sqb[5] - 2.0f * acc[a][5], 1e-12f));
        o1.z = sqrtf(fmaxf(sqa[a] + sqb[6] - 2.0f * acc[a][6], 1e-12f));
        o1.w = sqrtf(fmaxf(sqa[a] + sqb[7] - 2.0f * acc[a][7], 1e-12f));
        *(float4*)&g_dist[(size_t)row * NPTS + colbase + tx * 8]     = o0;
        *(float4*)&g_dist[(size_t)row * NPTS + colbase + tx * 8 + 4] = o1;
    }
}

// ---------------- per-row: threshold (17th smallest) + masked sums --------
__global__ void __launch_bounds__(256) row_kernel() {
    const int i = blockIdx.x;
    const int tid = threadIdx.x;
    const int lane = tid & 31;
    const int wid = tid >> 5;
    const float INF = __int_as_float(0x7f800000);

    __shared__ float srow[NPTS];           // 32 KB
    __shared__ unsigned char slab[NPTS];   // 8 KB
    __shared__ float rv[8];
    __shared__ int ri[8];
    __shared__ float selv[17];
    __shared__ int seli[17];
    __shared__ float sps[8], sns[8];
    __shared__ int scp[8], scn[8], sfp[8], san[8];

    const float* drow = g_dist + (size_t)i * NPTS;
    for (int j = tid; j < NPTS; j += 256) {
        srow[j] = (j == i) ? INF : drow[j];
        slab[j] = g_lab[j];
    }
    __syncthreads();

    // extract the 17 smallest (0-based index 16 of the sorted row = threshold)
    for (int t = 0; t < 17; t++) {
        float mv = INF;
        int mi = NPTS;
        for (int j = tid; j < NPTS; j += 256) {
            float v = srow[j];
            if (v < mv) { mv = v; mi = j; }
        }
#pragma unroll
        for (int off = 16; off; off >>= 1) {
            float ov = __shfl_down_sync(0xffffffffu, mv, off);
            int   oi = __shfl_down_sync(0xffffffffu, mi, off);
            if (ov < mv || (ov == mv && oi < mi)) { mv = ov; mi = oi; }
        }
        if (lane == 0) { rv[wid] = mv; ri[wid] = mi; }
        __syncthreads();
        if (tid == 0) {
            float bv = rv[0]; int bi = ri[0];
            for (int w = 1; w < 8; w++)
                if (rv[w] < bv || (rv[w] == bv && ri[w] < bi)) { bv = rv[w]; bi = ri[w]; }
            selv[t] = bv; seli[t] = bi;
            srow[bi] = INF;  // remove so next extraction finds the next one
        }
        __syncthreads();
    }
    // restore the extracted values (the sums need them)
    if (tid < 17) srow[seli[tid]] = selv[tid];
    __syncthreads();

    const float thr = selv[16];
    const int myl = slab[i];

    float ps = 0.0f, ns = 0.0f;
    int cp = 0, cn = 0, fp = NPTS, anyneg = 0;
    for (int j = tid; j < NPTS; j += 256) {
        if (j == i) continue;
        float dv = srow[j];
        bool below = dv < thr;
        if (slab[j] == myl) {
            if (j < fp) fp = j;
            if (below) { ps += expf(-dv); cp++; }
        } else {
            anyneg = 1;
            if (below) { ns += expf(-dv); cn++; }
        }
    }
#pragma unroll
    for (int off = 16; off; off >>= 1) {
        ps += __shfl_down_sync(0xffffffffu, ps, off);
        ns += __shfl_down_sync(0xffffffffu, ns, off);
        cp += __shfl_down_sync(0xffffffffu, cp, off);
        cn += __shfl_down_sync(0xffffffffu, cn, off);
        int ofp = __shfl_down_sync(0xffffffffu, fp, off);
        fp = min(fp, ofp);
        anyneg |= __shfl_down_sync(0xffffffffu, anyneg, off);
    }
    if (lane == 0) { sps[wid] = ps; sns[wid] = ns; scp[wid] = cp; scn[wid] = cn; sfp[wid] = fp; san[wid] = anyneg; }
    __syncthreads();
    if (tid == 0) {
        ps = 0; ns = 0; cp = 0; cn = 0; fp = NPTS; anyneg = 0;
        for (int w = 0; w < 8; w++) {
            ps += sps[w]; ns += sns[w]; cp += scp[w]; cn += scn[w];
            fp = min(fp, sfp[w]); anyneg |= san[w];
        }
        bool haspos = (fp < NPTS);
        bool validr = haspos && (anyneg != 0);
        float pos_eff = (cp == 0) ? (haspos ? expf(-srow[fp]) : 1.0f) : ps;
        float loss_i = validr ? logf((pos_eff + ns) / pos_eff) : 0.0f;
        int cpa = (cp == 0) ? 1 : cp;
        g_loss[i] = loss_i;
        g_accv[i] = (validr && cpa > cn) ? 1.0f : 0.0f;
        g_tpv[i]  = validr ? (float)cp : 0.0f;
        g_tnv[i]  = validr ? (float)cn : 0.0f;
    }
}

// ---------------- deterministic final reduction ----------------
__global__ void finalize_kernel(float* __restrict__ out) {
    __shared__ float s0[256], s1[256], s2[256], s3[256];
    int tid = threadIdx.x;
    float a = 0, b = 0, c = 0, d = 0;
    for (int j = tid; j < NPTS; j += 256) {
        a += g_loss[j]; b += g_accv[j]; c += g_tpv[j]; d += g_tnv[j];
    }
    s0[tid] = a; s1[tid] = b; s2[tid] = c; s3[tid] = d;
    __syncthreads();
    for (int off = 128; off; off >>= 1) {
        if (tid < off) {
            s0[tid] += s0[tid + off];
            s1[tid] += s1[tid + off];
            s2[tid] += s2[tid + off];
            s3[tid] += s3[tid + off];
        }
        __syncthreads();
    }
    if (tid == 0) {
        const float inv = 1.0f / (float)NPTS;
        out[0] = s0[0] * inv;  // loss
        out[1] = s1[0] * inv;  // accuracy
        out[2] = s2[0] * inv;  // tp
        out[3] = s3[0] * inv;  // tn
    }
}

extern "C" void kernel_launch(void* const* d_in, const int* in_sizes, int n_in,
                              void* d_out, int out_size) {
    const float* X = (const float*)d_in[0];
    const void* T = d_in[1];
    float* out = (float*)d_out;
    (void)in_sizes; (void)n_in; (void)out_size;

    detect_kernel<<<1, 256>>>((const int*)T);
    conv_kernel<<<(NPTS + 255) / 256, 256>>>(T);
    sq_kernel<<<NPTS, 128>>>(X);
    dim3 grid(NPTS / 128, NPTS / 128);
    dist_kernel<<<grid, 256>>>(X);
    row_kernel<<<NPTS, 256>>>();
    finalize_kernel<<<1, 256>>>(out);
}

// round 5
// speedup vs baseline: 1.0035x; 1.0035x over previous
#include <cuda_runtime.h>
#include <math.h>

#define NPTS 8192
#define DIM  128

// ---------------- device scratch (no allocations allowed) ----------------
__device__ float         g_dist[(size_t)NPTS * NPTS];  // 256 MB distance matrix
__device__ float         g_sq[NPTS];
__device__ unsigned char g_lab[NPTS];
__device__ float         g_loss[NPTS];
__device__ float         g_accv[NPTS];
__device__ float         g_tpv[NPTS];
__device__ float         g_tnv[NPTS];
__device__ int           g_is32;

// ---------------- dtype detection for targets (int32 vs int64) -----------
// Labels are uniform in [0,128). If targets are int64 little-endian, every odd
// int32 slot (high word) is 0. If int32, odd slots are real labels and the OR
// over 4096 of them is nonzero with overwhelming certainty. Only reads the
// first 8192 int32 slots = 32KB, safe for either layout.
__global__ void detect_kernel(const int* __restrict__ t) {
    int local = 0;
    for (int j = threadIdx.x; j < 4096; j += blockDim.x) local |= t[2 * j + 1];
#pragma unroll
    for (int off = 16; off; off >>= 1) local |= __shfl_down_sync(0xffffffffu, local, off);
    __shared__ int s[8];
    if ((threadIdx.x & 31) == 0) s[threadIdx.x >> 5] = local;
    __syncthreads();
    if (threadIdx.x == 0) {
        int f = 0;
        for (int w = 0; w < 8; w++) f |= s[w];
        g_is32 = (f != 0);
    }
}

__global__ void conv_kernel(const void* __restrict__ t) {
    int is32 = g_is32;
    int i = blockIdx.x * blockDim.x + threadIdx.x;
    if (i < NPTS) {
        int v = is32 ? ((const int*)t)[i] : (int)(((const long long*)t)[i]);
        g_lab[i] = (unsigned char)v;
    }
}

// ---------------- squared norms ----------------
__global__ void sq_kernel(const float* __restrict__ X) {
    int i = blockIdx.x;
    int tid = threadIdx.x;  // 128 threads
    float v = X[i * DIM + tid];
    v *= v;
#pragma unroll
    for (int off = 16; off; off >>= 1) v += __shfl_down_sync(0xffffffffu, v, off);
    __shared__ float s[4];
    if ((tid & 31) == 0) s[tid >> 5] = v;
    __syncthreads();
    if (tid == 0) g_sq[i] = s[0] + s[1] + s[2] + s[3];
}

// ---------------- distance matrix: tiled fp32 "GEMM" ----------------
// 128x128 tile per block, 256 threads, 8x8 micro-tile per thread, BK=16.
__global__ void __launch_bounds__(256) dist_kernel(const float* __restrict__ X) {
    __shared__ float As[16][128];
    __shared__ float Bs[16][128];

    const int bx = blockIdx.x;  // column tile (j)
    const int by = blockIdx.y;  // row tile (i)
    const int tid = threadIdx.x;
    const int tx = tid & 15;
    const int ty = tid >> 4;
    const int rowbase = by * 128;
    const int colbase = bx * 128;

    float acc[8][8];
#pragma unroll
    for (int a = 0; a < 8; a++)
#pragma unroll
        for (int b = 0; b < 8; b++) acc[a][b] = 0.0f;

    for (int k0 = 0; k0 < DIM; k0 += 16) {
#pragma unroll
        for (int r = 0; r < 2; r++) {
            int pos = tid + r * 256;     // 0..511
            int row = pos >> 2;          // 0..127
            int kc  = pos & 3;           // 0..3 (float4 chunk within the 16 k's)
            float4 va = *(const float4*)&X[(size_t)(rowbase + row) * DIM + k0 + kc * 4];
            As[kc * 4 + 0][row] = va.x;
            As[kc * 4 + 1][row] = va.y;
            As[kc * 4 + 2][row] = va.z;
            As[kc * 4 + 3][row] = va.w;
            float4 vb = *(const float4*)&X[(size_t)(colbase + row) * DIM + k0 + kc * 4];
            Bs[kc * 4 + 0][row] = vb.x;
            Bs[kc * 4 + 1][row] = vb.y;
            Bs[kc * 4 + 2][row] = vb.z;
            Bs[kc * 4 + 3][row] = vb.w;
        }
        __syncthreads();
#pragma unroll
        for (int kk = 0; kk < 16; kk++) {
            float ar[8], br[8];
            *(float4*)&ar[0] = *(const float4*)&As[kk][ty * 8];
            *(float4*)&ar[4] = *(const float4*)&As[kk][ty * 8 + 4];
            *(float4*)&br[0] = *(const float4*)&Bs[kk][tx * 8];
            *(float4*)&br[4] = *(const float4*)&Bs[kk][tx * 8 + 4];
#pragma unroll
            for (int a = 0; a < 8; a++)
#pragma unroll
                for (int b = 0; b < 8; b++) acc[a][b] = fmaf(ar[a], br[b], acc[a][b]);
        }
        __syncthreads();
    }

    float sqa[8], sqb[8];
#pragma unroll
    for (int a = 0; a < 8; a++) sqa[a] = g_sq[rowbase + ty * 8 + a];
#pragma unroll
    for (int b = 0; b < 8; b++) sqb[b] = g_sq[colbase + tx * 8 + b];

#pragma unroll
    for (int a = 0; a < 8; a++) {
        int row = rowbase + ty * 8 + a;
        float4 o0, o1;
        o0.x = sqrtf(fmaxf(sqa[a] + sqb[0] - 2.0f * acc[a][0], 1e-12f));
        o0.y = sqrtf(fmaxf(sqa[a] + sqb[1] - 2.0f * acc[a][1], 1e-12f));
        o0.z = sqrtf(fmaxf(sqa[a] + sqb[2] - 2.0f * acc[a][2], 1e-12f));
        o0.w = sqrtf(fmaxf(sqa[a] + sqb[3] - 2.0f * acc[a][3], 1e-12f));
        o1.x = sqrtf(fmaxf(sqa[a] + sqb[4] - 2.0f * acc[a][4], 1e-12f));
        o1.y = sqrtf(fmaxf(sqa[a] + sqb[5] - 2.0f * acc[a][5], 1e-12f));
        o1.z = sqrtf(fmaxf(sqa[a] + sqb[6] - 2.0f * acc[a][6], 1e-12f));
        o1.w = sqrtf(fmaxf(sqa[a] + sqb[7] - 2.0f * acc[a][7], 1e-12f));
        *(float4*)&g_dist[(size_t)row * NPTS + colbase + tx * 8]     = o0;
        *(float4*)&g_dist[(size_t)row * NPTS + colbase + tx * 8 + 4] = o1;
    }
}

// ---------------- per-row: threshold (17th smallest) + masked sums --------
__global__ void __launch_bounds__(256) row_kernel() {
    const int i = blockIdx.x;
    const int tid = threadIdx.x;
    const int lane = tid & 31;
    const int wid = tid >> 5;
    const float INF = __int_as_float(0x7f800000);

    __shared__ float srow[NPTS];           // 32 KB
    __shared__ unsigned char slab[NPTS];   // 8 KB
    __shared__ float rv[8];
    __shared__ int ri[8];
    __shared__ float selv[17];
    __shared__ int seli[17];
    __shared__ float sps[8], sns[8];
    __shared__ int scp[8], scn[8], sfp[8], san[8];

    const float* drow = g_dist + (size_t)i * NPTS;
    for (int j = tid; j < NPTS; j += 256) {
        srow[j] = (j == i) ? INF : drow[j];
        slab[j] = g_lab[j];
    }
    __syncthreads();

    // extract the 17 smallest (0-based index 16 of the sorted row = threshold)
    for (int t = 0; t < 17; t++) {
        float mv = INF;
        int mi = NPTS;
        for (int j = tid; j < NPTS; j += 256) {
            float v = srow[j];
            if (v < mv) { mv = v; mi = j; }
        }
#pragma unroll
        for (int off = 16; off; off >>= 1) {
            float ov = __shfl_down_sync(0xffffffffu, mv, off);
            int   oi = __shfl_down_sync(0xffffffffu, mi, off);
            if (ov < mv || (ov == mv && oi < mi)) { mv = ov; mi = oi; }
        }
        if (lane == 0) { rv[wid] = mv; ri[wid] = mi; }
        __syncthreads();
        if (tid == 0) {
            float bv = rv[0]; int bi = ri[0];
            for (int w = 1; w < 8; w++)
                if (rv[w] < bv || (rv[w] == bv && ri[w] < bi)) { bv = rv[w]; bi = ri[w]; }
            selv[t] = bv; seli[t] = bi;
            srow[bi] = INF;  // remove so next extraction finds the next one
        }
        __syncthreads();
    }
    // restore the extracted values (the sums need them)
    if (tid < 17) srow[seli[tid]] = selv[tid];
    __syncthreads();

    const float thr = selv[16];
    const int myl = slab[i];

    float ps = 0.0f, ns = 0.0f;
    int cp = 0, cn = 0, fp = NPTS, anyneg = 0;
    for (int j = tid; j < NPTS; j += 256) {
        if (j == i) continue;
        float dv = srow[j];
        bool below = dv < thr;
        if (slab[j] == myl) {
            if (j < fp) fp = j;
            if (below) { ps += expf(-dv); cp++; }
        } else {
            anyneg = 1;
            if (below) { ns += expf(-dv); cn++; }
        }
    }
#pragma unroll
    for (int off = 16; off; off >>= 1) {
        ps += __shfl_down_sync(0xffffffffu, ps, off);
        ns += __shfl_down_sync(0xffffffffu, ns, off);
        cp += __shfl_down_sync(0xffffffffu, cp, off);
        cn += __shfl_down_sync(0xffffffffu, cn, off);
        int ofp = __shfl_down_sync(0xffffffffu, fp, off);
        fp = min(fp, ofp);
        anyneg |= __shfl_down_sync(0xffffffffu, anyneg, off);
    }
    if (lane == 0) { sps[wid] = ps; sns[wid] = ns; scp[wid] = cp; scn[wid] = cn; sfp[wid] = fp; san[wid] = anyneg; }
    __syncthreads();
    if (tid == 0) {
        ps = 0; ns = 0; cp = 0; cn = 0; fp = NPTS; anyneg = 0;
        for (int w = 0; w < 8; w++) {
            ps += sps[w]; ns += sns[w]; cp += scp[w]; cn += scn[w];
            fp = min(fp, sfp[w]); anyneg |= san[w];
        }
        bool haspos = (fp < NPTS);
        bool validr = haspos && (anyneg != 0);
        float pos_eff = (cp == 0) ? (haspos ? expf(-srow[fp]) : 1.0f) : ps;
        float loss_i = validr ? logf((pos_eff + ns) / pos_eff) : 0.0f;
        int cpa = (cp == 0) ? 1 : cp;
        g_loss[i] = loss_i;
        g_accv[i] = (validr && cpa > cn) ? 1.0f : 0.0f;
        g_tpv[i]  = validr ? (float)cp : 0.0f;
        g_tnv[i]  = validr ? (float)cn : 0.0f;
    }
}

// ---------------- deterministic final reduction ----------------
__global__ void finalize_kernel(float* __restrict__ out) {
    __shared__ float s0[256], s1[256], s2[256], s3[256];
    int tid = threadIdx.x;
    float a = 0, b = 0, c = 0, d = 0;
    for (int j = tid; j < NPTS; j += 256) {
        a += g_loss[j]; b += g_accv[j]; c += g_tpv[j]; d += g_tnv[j];
    }
    s0[tid] = a; s1[tid] = b; s2[tid] = c; s3[tid] = d;
    __syncthreads();
    for (int off = 128; off; off >>= 1) {
        if (tid < off) {
            s0[tid] += s0[tid + off];
            s1[tid] += s1[tid + off];
            s2[tid] += s2[tid + off];
            s3[tid] += s3[tid + off];
        }
        __syncthreads();
    }
    if (tid == 0) {
        const float inv = 1.0f / (float)NPTS;
        out[0] = s0[0] * inv;  // loss
        out[1] = s1[0] * inv;  // accuracy
        out[2] = s2[0] * inv;  // tp
        out[3] = s3[0] * inv;  // tn
    }
}

extern "C" void kernel_launch(void* const* d_in, const int* in_sizes, int n_in,
                              void* d_out, int out_size) {
    const float* X = (const float*)d_in[0];
    const void* T = d_in[1];
    float* out = (float*)d_out;
    (void)in_sizes; (void)n_in; (void)out_size;

    detect_kernel<<<1, 256>>>((const int*)T);
    conv_kernel<<<(NPTS + 255) / 256, 256>>>(T);
    sq_kernel<<<NPTS, 128>>>(X);
    dim3 grid(NPTS / 128, NPTS / 128);
    dist_kernel<<<grid, 256>>>(X);
    row_kernel<<<NPTS, 256>>>();
    finalize_kernel<<<1, 256>>>(out);
}

// round 6
// speedup vs baseline: 1.2853x; 1.2808x over previous
#include <cuda_runtime.h>
#include <math.h>

#define NPTS 8192
#define DIM  128

// ---------------- device scratch (no allocations allowed) ----------------
__device__ float         g_dist[(size_t)NPTS * NPTS];  // 256 MB distance matrix
__device__ float         g_sq[NPTS];
__device__ unsigned char g_lab[NPTS];
__device__ float         g_loss[NPTS];
__device__ float         g_accv[NPTS];
__device__ float         g_tpv[NPTS];
__device__ float         g_tnv[NPTS];
__device__ int           g_is32;

// ---------------- dtype detection for targets (int32 vs int64) -----------
__global__ void detect_kernel(const int* __restrict__ t) {
    int local = 0;
    for (int j = threadIdx.x; j < 4096; j += blockDim.x) local |= t[2 * j + 1];
#pragma unroll
    for (int off = 16; off; off >>= 1) local |= __shfl_down_sync(0xffffffffu, local, off);
    __shared__ int s[8];
    if ((threadIdx.x & 31) == 0) s[threadIdx.x >> 5] = local;
    __syncthreads();
    if (threadIdx.x == 0) {
        int f = 0;
        for (int w = 0; w < 8; w++) f |= s[w];
        g_is32 = (f != 0);
    }
}

__global__ void conv_kernel(const void* __restrict__ t) {
    int is32 = g_is32;
    int i = blockIdx.x * blockDim.x + threadIdx.x;
    if (i < NPTS) {
        int v = is32 ? ((const int*)t)[i] : (int)(((const long long*)t)[i]);
        g_lab[i] = (unsigned char)v;
    }
}

// ---------------- squared norms ----------------
__global__ void sq_kernel(const float* __restrict__ X) {
    int i = blockIdx.x;
    int tid = threadIdx.x;  // 128 threads
    float v = X[i * DIM + tid];
    v *= v;
#pragma unroll
    for (int off = 16; off; off >>= 1) v += __shfl_down_sync(0xffffffffu, v, off);
    __shared__ float s[4];
    if ((tid & 31) == 0) s[tid >> 5] = v;
    __syncthreads();
    if (tid == 0) g_sq[i] = s[0] + s[1] + s[2] + s[3];
}

// ---------------- distance matrix: symmetric tiled fp32 "GEMM" ----------------
// Only upper-triangular 128x128 tiles computed (2080 instead of 4096);
// each tile is written twice (normal + transposed) -> exact symmetry, half FMA.
__global__ void __launch_bounds__(256) dist_kernel(const float* __restrict__ X) {
    __shared__ float As[16][128];
    __shared__ float Bs[16][128];

    // invert triangular block index: t -> (by, bx) with by <= bx
    const int t = blockIdx.x;
    int b = (int)((sqrtf(8.0f * (float)t + 1.0f) - 1.0f) * 0.5f);
    while ((b * (b + 1)) / 2 > t) b--;
    while (((b + 1) * (b + 2)) / 2 <= t) b++;
    const int by = t - (b * (b + 1)) / 2;   // row tile
    const int bx = b;                       // col tile (>= by)

    const int tid = threadIdx.x;
    const int tx = tid & 15;
    const int ty = tid >> 4;
    const int rowbase = by * 128;
    const int colbase = bx * 128;

    float acc[8][8];
#pragma unroll
    for (int a = 0; a < 8; a++)
#pragma unroll
        for (int c = 0; c < 8; c++) acc[a][c] = 0.0f;

    for (int k0 = 0; k0 < DIM; k0 += 16) {
#pragma unroll
        for (int r = 0; r < 2; r++) {
            int pos = tid + r * 256;     // 0..511
            int row = pos >> 2;          // 0..127
            int kc  = pos & 3;           // float4 chunk within the 16 k's
            float4 va = *(const float4*)&X[(size_t)(rowbase + row) * DIM + k0 + kc * 4];
            As[kc * 4 + 0][row] = va.x;
            As[kc * 4 + 1][row] = va.y;
            As[kc * 4 + 2][row] = va.z;
            As[kc * 4 + 3][row] = va.w;
            float4 vb = *(const float4*)&X[(size_t)(colbase + row) * DIM + k0 + kc * 4];
            Bs[kc * 4 + 0][row] = vb.x;
            Bs[kc * 4 + 1][row] = vb.y;
            Bs[kc * 4 + 2][row] = vb.z;
            Bs[kc * 4 + 3][row] = vb.w;
        }
        __syncthreads();
#pragma unroll
        for (int kk = 0; kk < 16; kk++) {
            float ar[8], br[8];
            *(float4*)&ar[0] = *(const float4*)&As[kk][ty * 8];
            *(float4*)&ar[4] = *(const float4*)&As[kk][ty * 8 + 4];
            *(float4*)&br[0] = *(const float4*)&Bs[kk][tx * 8];
            *(float4*)&br[4] = *(const float4*)&Bs[kk][tx * 8 + 4];
#pragma unroll
            for (int a = 0; a < 8; a++)
#pragma unroll
                for (int c = 0; c < 8; c++) acc[a][c] = fmaf(ar[a], br[c], acc[a][c]);
        }
        __syncthreads();
    }

    float sqa[8], sqb[8];
#pragma unroll
    for (int a = 0; a < 8; a++) sqa[a] = g_sq[rowbase + ty * 8 + a];
#pragma unroll
    for (int c = 0; c < 8; c++) sqb[c] = g_sq[colbase + tx * 8 + c];

    // convert Gram -> distance in place (values reused for both writes)
#pragma unroll
    for (int a = 0; a < 8; a++)
#pragma unroll
        for (int c = 0; c < 8; c++)
            acc[a][c] = sqrtf(fmaxf(sqa[a] + sqb[c] - 2.0f * acc[a][c], 1e-12f));

    // normal write: rows rowbase+ty*8+a, cols colbase+tx*8.. (coalesced float4)
#pragma unroll
    for (int a = 0; a < 8; a++) {
        int row = rowbase + ty * 8 + a;
        float4 o0 = make_float4(acc[a][0], acc[a][1], acc[a][2], acc[a][3]);
        float4 o1 = make_float4(acc[a][4], acc[a][5], acc[a][6], acc[a][7]);
        *(float4*)&g_dist[(size_t)row * NPTS + colbase + tx * 8]     = o0;
        *(float4*)&g_dist[(size_t)row * NPTS + colbase + tx * 8 + 4] = o1;
    }

    // transposed write (skip diagonal tiles): 32B contiguous per thread per col
    if (bx != by) {
#pragma unroll
        for (int c = 0; c < 8; c++) {
            int col = colbase + tx * 8 + c;
            float4 p0 = make_float4(acc[0][c], acc[1][c], acc[2][c], acc[3][c]);
            float4 p1 = make_float4(acc[4][c], acc[5][c], acc[6][c], acc[7][c]);
            *(float4*)&g_dist[(size_t)col * NPTS + rowbase + ty * 8]     = p0;
            *(float4*)&g_dist[(size_t)col * NPTS + rowbase + ty * 8 + 4] = p1;
        }
    }
}

// ---------------- per-row kernel: exact radix-select threshold + masked sums ---
// Positive fp32 bit patterns are order-isomorphic to values, so the 17th
// smallest is found EXACTLY via 3 histogram levels over bit fields 11+11+9.

__device__ __forceinline__ void hadd_agg(int* hist, int key, int lane) {
    // warp-aggregated histogram add; key == -1 means "no contribution"
    unsigned m = __match_any_sync(0xffffffffu, key);
    if (key >= 0 && lane == (__ffs(m) - 1))
        atomicAdd(&hist[key], __popc(m));
}

// Find smallest bin with cumulative count >= rank. Writes *out_bin and
// *out_before (count strictly below that bin). nbins must be multiple of 256.
__device__ __forceinline__ void hist_select(int* hist, int nbins, int rank,
                                            int tid, int* scanbuf,
                                            int* out_bin, int* out_before) {
    const int chunk = nbins >> 8;
    const int base = tid * chunk;
    int s = 0;
    for (int c = 0; c < chunk; c++) s += hist[base + c];
    scanbuf[tid] = s;
    __syncthreads();
    for (int off = 1; off < 256; off <<= 1) {
        int v = (tid >= off) ? scanbuf[tid - off] : 0;
        __syncthreads();
        scanbuf[tid] += v;
        __syncthreads();
    }
    int incl = scanbuf[tid];
    int excl = incl - s;
    if (excl < rank && incl >= rank) {
        int cum = excl;
        for (int c = 0; c < chunk; c++) {
            int h = hist[base + c];
            cum += h;
            if (cum >= rank) { *out_bin = base + c; *out_before = cum - h; break; }
        }
    }
    __syncthreads();
}

__global__ void __launch_bounds__(256) row_kernel() {
    const int i = blockIdx.x;
    const int tid = threadIdx.x;
    const int lane = tid & 31;
    const int wid = tid >> 5;
    const float INF = __int_as_float(0x7f800000);

    __shared__ float srow[NPTS];     // 32 KB
    __shared__ int   hist[2048];     // 8 KB (reused across the 3 levels)
    __shared__ int   scanbuf[256];
    __shared__ int   s_bin, s_before;
    __shared__ float sps[8], sns[8];
    __shared__ int scp[8], scn[8], sfp[8], san[8];

    // load row (vectorized), mask diagonal with +inf
    const float4* drow4 = (const float4*)(g_dist + (size_t)i * NPTS);
    for (int j4 = tid; j4 < NPTS / 4; j4 += 256)
        *(float4*)&srow[j4 * 4] = drow4[j4];
    __syncthreads();
    if (tid == 0) srow[i] = INF;
    __syncthreads();

    int rank = 17;  // (K+1)-th smallest

    // ---- level 1: bits >> 20 (2048 bins; all positive floats < 2^31) ----
    for (int c = tid; c < 2048; c += 256) hist[c] = 0;
    __syncthreads();
    for (int j = tid; j < NPTS; j += 256) {
        unsigned bits = __float_as_uint(srow[j]);
        hadd_agg(hist, (int)(bits >> 20), lane);
    }
    __syncthreads();
    hist_select(hist, 2048, rank, tid, scanbuf, &s_bin, &s_before);
    const int b1 = s_bin;
    rank -= s_before;
    __syncthreads();

    // ---- level 2: (bits >> 9) & 0x7FF, within coarse bin b1 ----
    for (int c = tid; c < 2048; c += 256) hist[c] = 0;
    __syncthreads();
    for (int j = tid; j < NPTS; j += 256) {
        unsigned bits = __float_as_uint(srow[j]);
        int key = ((int)(bits >> 20) == b1) ? (int)((bits >> 9) & 0x7FF) : -1;
        hadd_agg(hist, key, lane);
    }
    __syncthreads();
    hist_select(hist, 2048, rank, tid, scanbuf, &s_bin, &s_before);
    const int b2 = s_bin;
    rank -= s_before;
    __syncthreads();

    // ---- level 3: bits & 0x1FF, within (b1,b2) ----
    for (int c = tid; c < 512; c += 256) hist[c] = 0;
    __syncthreads();
    const unsigned hi20 = ((unsigned)b1 << 11) | (unsigned)b2;
    for (int j = tid; j < NPTS; j += 256) {
        unsigned bits = __float_as_uint(srow[j]);
        int key = ((bits >> 9) == hi20) ? (int)(bits & 0x1FF) : -1;
        hadd_agg(hist, key, lane);
    }
    __syncthreads();
    hist_select(hist, 512, rank, tid, scanbuf, &s_bin, &s_before);
    const int b3 = s_bin;
    __syncthreads();

    // exact bit pattern of the 17th smallest distance
    const float thr = __uint_as_float(((unsigned)b1 << 20) | ((unsigned)b2 << 9) | (unsigned)b3);
    const int myl = g_lab[i];

    // ---- masked sums (strict dist < thr, matching reference) ----
    float ps = 0.0f, ns = 0.0f;
    int cp = 0, cn = 0, fp = NPTS, anyneg = 0;
    for (int j = tid; j < NPTS; j += 256) {
        if (j == i) continue;
        float dv = srow[j];
        bool below = dv < thr;
        if (g_lab[j] == myl) {
            if (j < fp) fp = j;
            if (below) { ps += expf(-dv); cp++; }
        } else {
            anyneg = 1;
            if (below) { ns += expf(-dv); cn++; }
        }
    }
#pragma unroll
    for (int off = 16; off; off >>= 1) {
        ps += __shfl_down_sync(0xffffffffu, ps, off);
        ns += __shfl_down_sync(0xffffffffu, ns, off);
        cp += __shfl_down_sync(0xffffffffu, cp, off);
        cn += __shfl_down_sync(0xffffffffu, cn, off);
        int ofp = __shfl_down_sync(0xffffffffu, fp, off);
        fp = min(fp, ofp);
        anyneg |= __shfl_down_sync(0xffffffffu, anyneg, off);
    }
    if (lane == 0) { sps[wid] = ps; sns[wid] = ns; scp[wid] = cp; scn[wid] = cn; sfp[wid] = fp; san[wid] = anyneg; }
    __syncthreads();
    if (tid == 0) {
        ps = 0; ns = 0; cp = 0; cn = 0; fp = NPTS; anyneg = 0;
        for (int w = 0; w < 8; w++) {
            ps += sps[w]; ns += sns[w]; cp += scp[w]; cn += scn[w];
            fp = min(fp, sfp[w]); anyneg |= san[w];
        }
        bool haspos = (fp < NPTS);
        bool validr = haspos && (anyneg != 0);
        float pos_eff = (cp == 0) ? (haspos ? expf(-srow[fp]) : 1.0f) : ps;
        float loss_i = validr ? logf((pos_eff + ns) / pos_eff) : 0.0f;
        int cpa = (cp == 0) ? 1 : cp;
        g_loss[i] = loss_i;
        g_accv[i] = (validr && cpa > cn) ? 1.0f : 0.0f;
        g_tpv[i]  = validr ? (float)cp : 0.0f;
        g_tnv[i]  = validr ? (float)cn : 0.0f;
    }
}

// ---------------- deterministic final reduction ----------------
__global__ void finalize_kernel(float* __restrict__ out) {
    __shared__ float s0[256], s1[256], s2[256], s3[256];
    int tid = threadIdx.x;
    float a = 0, b = 0, c = 0, d = 0;
    for (int j = tid; j < NPTS; j += 256) {
        a += g_loss[j]; b += g_accv[j]; c += g_tpv[j]; d += g_tnv[j];
    }
    s0[tid] = a; s1[tid] = b; s2[tid] = c; s3[tid] = d;
    __syncthreads();
    for (int off = 128; off; off >>= 1) {
        if (tid < off) {
            s0[tid] += s0[tid + off];
            s1[tid] += s1[tid + off];
            s2[tid] += s2[tid + off];
            s3[tid] += s3[tid + off];
        }
        __syncthreads();
    }
    if (tid == 0) {
        const float inv = 1.0f / (float)NPTS;
        out[0] = s0[0] * inv;  // loss
        out[1] = s1[0] * inv;  // accuracy
        out[2] = s2[0] * inv;  // tp
        out[3] = s3[0] * inv;  // tn
    }
}

extern "C" void kernel_launch(void* const* d_in, const int* in_sizes, int n_in,
                              void* d_out, int out_size) {
    const float* X = (const float*)d_in[0];
    const void* T = d_in[1];
    float* out = (float*)d_out;
    (void)in_sizes; (void)n_in; (void)out_size;

    detect_kernel<<<1, 256>>>((const int*)T);
    conv_kernel<<<(NPTS + 255) / 256, 256>>>(T);
    sq_kernel<<<NPTS, 128>>>(X);
    const int ntiles = (NPTS / 128) * (NPTS / 128 + 1) / 2;  // 2080 triangular tiles
    dist_kernel<<<ntiles, 256>>>(X);
    row_kernel<<<NPTS, 256>>>();
    finalize_kernel<<<1, 256>>>(out);
}

// round 7
// speedup vs baseline: 1.3524x; 1.0522x over previous
#include <cuda_runtime.h>
#include <math.h>

#define NPTS 8192
#define DIM  128

// ---------------- device scratch (no allocations allowed) ----------------
__device__ float         g_dist[(size_t)NPTS * NPTS];  // 256 MB distance matrix
__device__ float         g_sq[NPTS];
__device__ unsigned char g_lab[NPTS];
__device__ float         g_loss[NPTS];
__device__ float         g_accv[NPTS];
__device__ float         g_tpv[NPTS];
__device__ float         g_tnv[NPTS];
__device__ int           g_is32;

// ---------------- packed fp32x2 helpers (Blackwell FFMA2 path) -----------
__device__ __forceinline__ void fma2(unsigned long long& d,
                                     unsigned long long a,
                                     unsigned long long b) {
    asm("fma.rn.f32x2 %0, %1, %2, %0;" : "+l"(d) : "l"(a), "l"(b));
}
__device__ __forceinline__ unsigned long long pack2(float lo, float hi) {
    unsigned long long r;
    asm("mov.b64 %0, {%1, %2};" : "=l"(r) : "r"(__float_as_uint(lo)), "r"(__float_as_uint(hi)));
    return r;
}
__device__ __forceinline__ void unpack2(unsigned long long v, float& lo, float& hi) {
    unsigned a, b;
    asm("mov.b64 {%0, %1}, %2;" : "=r"(a), "=r"(b) : "l"(v));
    lo = __uint_as_float(a);
    hi = __uint_as_float(b);
}

// ---------------- dtype detection for targets (int32 vs int64) -----------
__global__ void detect_kernel(const int* __restrict__ t) {
    int local = 0;
    for (int j = threadIdx.x; j < 4096; j += blockDim.x) local |= t[2 * j + 1];
#pragma unroll
    for (int off = 16; off; off >>= 1) local |= __shfl_down_sync(0xffffffffu, local, off);
    __shared__ int s[8];
    if ((threadIdx.x & 31) == 0) s[threadIdx.x >> 5] = local;
    __syncthreads();
    if (threadIdx.x == 0) {
        int f = 0;
        for (int w = 0; w < 8; w++) f |= s[w];
        g_is32 = (f != 0);
    }
}

__global__ void conv_kernel(const void* __restrict__ t) {
    int is32 = g_is32;
    int i = blockIdx.x * blockDim.x + threadIdx.x;
    if (i < NPTS) {
        int v = is32 ? ((const int*)t)[i] : (int)(((const long long*)t)[i]);
        g_lab[i] = (unsigned char)v;
    }
}

// ---------------- squared norms ----------------
__global__ void sq_kernel(const float* __restrict__ X) {
    int i = blockIdx.x;
    int tid = threadIdx.x;  // 128 threads
    float v = X[i * DIM + tid];
    v *= v;
#pragma unroll
    for (int off = 16; off; off >>= 1) v += __shfl_down_sync(0xffffffffu, v, off);
    __shared__ float s[4];
    if ((tid & 31) == 0) s[tid >> 5] = v;
    __syncthreads();
    if (tid == 0) g_sq[i] = s[0] + s[1] + s[2] + s[3];
}

// ---------------- distance matrix: symmetric tiled fp32x2 "GEMM" ----------
// Upper-triangular 128x128 tiles only (2080), written twice. Inner product
// uses packed fma.rn.f32x2 (FFMA2) -> 2 MACs per fma-pipe slot.
__global__ void __launch_bounds__(256) dist_kernel(const float* __restrict__ X) {
    __shared__ float As[16][128];
    __shared__ float Bs[16][128];

    // invert triangular block index: t -> (by, bx) with by <= bx
    const int t = blockIdx.x;
    int b = (int)((sqrtf(8.0f * (float)t + 1.0f) - 1.0f) * 0.5f);
    while ((b * (b + 1)) / 2 > t) b--;
    while (((b + 1) * (b + 2)) / 2 <= t) b++;
    const int by = t - (b * (b + 1)) / 2;   // row tile
    const int bx = b;                       // col tile (>= by)

    const int tid = threadIdx.x;
    const int tx = tid & 15;
    const int ty = tid >> 4;
    const int rowbase = by * 128;
    const int colbase = bx * 128;

    unsigned long long acc2[8][4];  // [a][c2] = cols (2*c2, 2*c2+1)
#pragma unroll
    for (int a = 0; a < 8; a++)
#pragma unroll
        for (int c = 0; c < 4; c++) acc2[a][c] = 0ull;

    for (int k0 = 0; k0 < DIM; k0 += 16) {
#pragma unroll
        for (int r = 0; r < 2; r++) {
            int pos = tid + r * 256;     // 0..511
            int row = pos >> 2;          // 0..127
            int kc  = pos & 3;           // float4 chunk within the 16 k's
            float4 va = *(const float4*)&X[(size_t)(rowbase + row) * DIM + k0 + kc * 4];
            As[kc * 4 + 0][row] = va.x;
            As[kc * 4 + 1][row] = va.y;
            As[kc * 4 + 2][row] = va.z;
            As[kc * 4 + 3][row] = va.w;
            float4 vb = *(const float4*)&X[(size_t)(colbase + row) * DIM + k0 + kc * 4];
            Bs[kc * 4 + 0][row] = vb.x;
            Bs[kc * 4 + 1][row] = vb.y;
            Bs[kc * 4 + 2][row] = vb.z;
            Bs[kc * 4 + 3][row] = vb.w;
        }
        __syncthreads();
#pragma unroll
        for (int kk = 0; kk < 16; kk++) {
            float ar[8], br[8];
            *(float4*)&ar[0] = *(const float4*)&As[kk][ty * 8];
            *(float4*)&ar[4] = *(const float4*)&As[kk][ty * 8 + 4];
            *(float4*)&br[0] = *(const float4*)&Bs[kk][tx * 8];
            *(float4*)&br[4] = *(const float4*)&Bs[kk][tx * 8 + 4];
            unsigned long long b2[4];
#pragma unroll
            for (int c = 0; c < 4; c++) b2[c] = pack2(br[2 * c], br[2 * c + 1]);
#pragma unroll
            for (int a = 0; a < 8; a++) {
                unsigned long long a2 = pack2(ar[a], ar[a]);
#pragma unroll
                for (int c = 0; c < 4; c++) fma2(acc2[a][c], a2, b2[c]);
            }
        }
        __syncthreads();
    }

    float sqa[8], sqb[8];
#pragma unroll
    for (int a = 0; a < 8; a++) sqa[a] = g_sq[rowbase + ty * 8 + a];
#pragma unroll
    for (int c = 0; c < 8; c++) sqb[c] = g_sq[colbase + tx * 8 + c];

    float acc[8][8];
#pragma unroll
    for (int a = 0; a < 8; a++)
#pragma unroll
        for (int c = 0; c < 4; c++) {
            float lo, hi;
            unpack2(acc2[a][c], lo, hi);
            acc[a][2 * c]     = sqrtf(fmaxf(sqa[a] + sqb[2 * c]     - 2.0f * lo, 1e-12f));
            acc[a][2 * c + 1] = sqrtf(fmaxf(sqa[a] + sqb[2 * c + 1] - 2.0f * hi, 1e-12f));
        }

    // normal write: coalesced float4
#pragma unroll
    for (int a = 0; a < 8; a++) {
        int row = rowbase + ty * 8 + a;
        float4 o0 = make_float4(acc[a][0], acc[a][1], acc[a][2], acc[a][3]);
        float4 o1 = make_float4(acc[a][4], acc[a][5], acc[a][6], acc[a][7]);
        *(float4*)&g_dist[(size_t)row * NPTS + colbase + tx * 8]     = o0;
        *(float4*)&g_dist[(size_t)row * NPTS + colbase + tx * 8 + 4] = o1;
    }

    // transposed write (skip diagonal tiles): 32B contiguous per (thread,col)
    if (bx != by) {
#pragma unroll
        for (int c = 0; c < 8; c++) {
            int col = colbase + tx * 8 + c;
            float4 p0 = make_float4(acc[0][c], acc[1][c], acc[2][c], acc[3][c]);
            float4 p1 = make_float4(acc[4][c], acc[5][c], acc[6][c], acc[7][c]);
            *(float4*)&g_dist[(size_t)col * NPTS + rowbase + ty * 8]     = p0;
            *(float4*)&g_dist[(size_t)col * NPTS + rowbase + ty * 8 + 4] = p1;
        }
    }
}

// ---------------- per-row kernel: exact radix-select threshold + masked sums ---

__device__ __forceinline__ void hadd_agg(int* hist, int key, int lane) {
    unsigned m = __match_any_sync(0xffffffffu, key);
    if (key >= 0 && lane == (__ffs(m) - 1))
        atomicAdd(&hist[key], __popc(m));
}

// Light scan select: 3 barriers instead of 17. nbins multiple of 256.
__device__ __forceinline__ void hist_select(int* hist, int nbins, int rank,
                                            int tid, int lane, int wid,
                                            int* wsum, int* wpre,
                                            int* out_bin, int* out_before) {
    const int chunk = nbins >> 8;
    const int base = tid * chunk;
    int s = 0;
    for (int c = 0; c < chunk; c++) s += hist[base + c];
    // inclusive scan of s within warp
    int incl = s;
#pragma unroll
    for (int off = 1; off < 32; off <<= 1) {
        int v = __shfl_up_sync(0xffffffffu, incl, off);
        if (lane >= off) incl += v;
    }
    if (lane == 31) wsum[wid] = incl;
    __syncthreads();
    if (tid < 8) {
        int v = wsum[tid];
        int p = v;
#pragma unroll
        for (int off = 1; off < 8; off <<= 1) {
            int u = __shfl_up_sync(0xffu, p, off, 8);
            if (tid >= off) p += u;
        }
        wpre[tid] = p - v;  // exclusive warp prefix
    }
    __syncthreads();
    int excl = wpre[wid] + incl - s;
    if (excl < rank && excl + s >= rank) {
        int cum = excl;
        for (int c = 0; c < chunk; c++) {
            int h = hist[base + c];
            cum += h;
            if (cum >= rank) { *out_bin = base + c; *out_before = cum - h; break; }
        }
    }
    __syncthreads();
}

__global__ void __launch_bounds__(256) row_kernel() {
    const int i = blockIdx.x;
    const int tid = threadIdx.x;
    const int lane = tid & 31;
    const int wid = tid >> 5;
    const float INF = __int_as_float(0x7f800000);

    __shared__ float srow[NPTS];     // 32 KB
    __shared__ int   hist[2048];     // 8 KB (reused across the 3 levels)
    __shared__ int   wsum[8], wpre[8];
    __shared__ int   s_bin, s_before;
    __shared__ float sps[8], sns[8];
    __shared__ int scp[8], scn[8], sfp[8], san[8];

    // zero level-1 histogram, then fused load + level-1 histogram pass
    for (int c = tid; c < 2048; c += 256) hist[c] = 0;
    __syncthreads();

    const float4* drow4 = (const float4*)(g_dist + (size_t)i * NPTS);
    for (int j4 = tid; j4 < NPTS / 4; j4 += 256) {
        float4 v = drow4[j4];
        int base = j4 * 4;
        if (i - base >= 0 && i - base < 4) {  // mask diagonal with +inf
            if (i - base == 0) v.x = INF;
            else if (i - base == 1) v.y = INF;
            else if (i - base == 2) v.z = INF;
            else v.w = INF;
        }
        *(float4*)&srow[base] = v;
        hadd_agg(hist, (int)(__float_as_uint(v.x) >> 20), lane);
        hadd_agg(hist, (int)(__float_as_uint(v.y) >> 20), lane);
        hadd_agg(hist, (int)(__float_as_uint(v.z) >> 20), lane);
        hadd_agg(hist, (int)(__float_as_uint(v.w) >> 20), lane);
    }
    __syncthreads();

    int rank = 17;  // (K+1)-th smallest
    hist_select(hist, 2048, rank, tid, lane, wid, wsum, wpre, &s_bin, &s_before);
    const int b1 = s_bin;
    rank -= s_before;
    __syncthreads();

    // ---- level 2: (bits >> 9) & 0x7FF within coarse bin b1 ----
    for (int c = tid; c < 2048; c += 256) hist[c] = 0;
    __syncthreads();
    for (int j = tid; j < NPTS; j += 256) {
        unsigned bits = __float_as_uint(srow[j]);
        int key = ((int)(bits >> 20) == b1) ? (int)((bits >> 9) & 0x7FF) : -1;
        hadd_agg(hist, key, lane);
    }
    __syncthreads();
    hist_select(hist, 2048, rank, tid, lane, wid, wsum, wpre, &s_bin, &s_before);
    const int b2 = s_bin;
    rank -= s_before;
    __syncthreads();

    // ---- level 3: bits & 0x1FF within (b1,b2) ----
    for (int c = tid; c < 512; c += 256) hist[c] = 0;
    __syncthreads();
    const unsigned hi20 = ((unsigned)b1 << 11) | (unsigned)b2;
    for (int j = tid; j < NPTS; j += 256) {
        unsigned bits = __float_as_uint(srow[j]);
        int key = ((bits >> 9) == hi20) ? (int)(bits & 0x1FF) : -1;
        hadd_agg(hist, key, lane);
    }
    __syncthreads();
    hist_select(hist, 512, rank, tid, lane, wid, wsum, wpre, &s_bin, &s_before);
    const int b3 = s_bin;
    __syncthreads();

    // exact bit pattern of the 17th smallest distance
    const float thr = __uint_as_float(((unsigned)b1 << 20) | ((unsigned)b2 << 9) | (unsigned)b3);
    const int myl = g_lab[i];

    // ---- masked sums (strict dist < thr, matching reference) ----
    float ps = 0.0f, ns = 0.0f;
    int cp = 0, cn = 0, fp = NPTS, anyneg = 0;
    for (int j = tid; j < NPTS; j += 256) {
        if (j == i) continue;
        float dv = srow[j];
        bool below = dv < thr;
        if (g_lab[j] == myl) {
            if (j < fp) fp = j;
            if (below) { ps += expf(-dv); cp++; }
        } else {
            anyneg = 1;
            if (below) { ns += expf(-dv); cn++; }
        }
    }
#pragma unroll
    for (int off = 16; off; off >>= 1) {
        ps += __shfl_down_sync(0xffffffffu, ps, off);
        ns += __shfl_down_sync(0xffffffffu, ns, off);
        cp += __shfl_down_sync(0xffffffffu, cp, off);
        cn += __shfl_down_sync(0xffffffffu, cn, off);
        int ofp = __shfl_down_sync(0xffffffffu, fp, off);
        fp = min(fp, ofp);
        anyneg |= __shfl_down_sync(0xffffffffu, anyneg, off);
    }
    if (lane == 0) { sps[wid] = ps; sns[wid] = ns; scp[wid] = cp; scn[wid] = cn; sfp[wid] = fp; san[wid] = anyneg; }
    __syncthreads();
    if (tid == 0) {
        ps = 0; ns = 0; cp = 0; cn = 0; fp = NPTS; anyneg = 0;
        for (int w = 0; w < 8; w++) {
            ps += sps[w]; ns += sns[w]; cp += scp[w]; cn += scn[w];
            fp = min(fp, sfp[w]); anyneg |= san[w];
        }
        bool haspos = (fp < NPTS);
        bool validr = haspos && (anyneg != 0);
        float pos_eff = (cp == 0) ? (haspos ? expf(-srow[fp]) : 1.0f) : ps;
        float loss_i = validr ? logf((pos_eff + ns) / pos_eff) : 0.0f;
        int cpa = (cp == 0) ? 1 : cp;
        g_loss[i] = loss_i;
        g_accv[i] = (validr && cpa > cn) ? 1.0f : 0.0f;
        g_tpv[i]  = validr ? (float)cp : 0.0f;
        g_tnv[i]  = validr ? (float)cn : 0.0f;
    }
}

// ---------------- deterministic final reduction ----------------
__global__ void finalize_kernel(float* __restrict__ out) {
    __shared__ float s0[256], s1[256], s2[256], s3[256];
    int tid = threadIdx.x;
    float a = 0, b = 0, c = 0, d = 0;
    for (int j = tid; j < NPTS; j += 256) {
        a += g_loss[j]; b += g_accv[j]; c += g_tpv[j]; d += g_tnv[j];
    }
    s0[tid] = a; s1[tid] = b; s2[tid] = c; s3[tid] = d;
    __syncthreads();
    for (int off = 128; off; off >>= 1) {
        if (tid < off) {
            s0[tid] += s0[tid + off];
            s1[tid] += s1[tid + off];
            s2[tid] += s2[tid + off];
            s3[tid] += s3[tid + off];
        }
        __syncthreads();
    }
    if (tid == 0) {
        const float inv = 1.0f / (float)NPTS;
        out[0] = s0[0] * inv;  // loss
        out[1] = s1[0] * inv;  // accuracy
        out[2] = s2[0] * inv;  // tp
        out[3] = s3[0] * inv;  // tn
    }
}

extern "C" void kernel_launch(void* const* d_in, const int* in_sizes, int n_in,
                              void* d_out, int out_size) {
    const float* X = (const float*)d_in[0];
    const void* T = d_in[1];
    float* out = (float*)d_out;
    (void)in_sizes; (void)n_in; (void)out_size;

    detect_kernel<<<1, 256>>>((const int*)T);
    conv_kernel<<<(NPTS + 255) / 256, 256>>>(T);
    sq_kernel<<<NPTS, 128>>>(X);
    const int ntiles = (NPTS / 128) * (NPTS / 128 + 1) / 2;  // 2080 triangular tiles
    dist_kernel<<<ntiles, 256>>>(X);
    row_kernel<<<NPTS, 256>>>();
    finalize_kernel<<<1, 256>>>(out);
}

// round 9
// speedup vs baseline: 1.5234x; 1.1265x over previous
#include <cuda_runtime.h>
#include <math.h>

#define NPTS 8192
#define DIM  128
#define CAND_MAX 1024

// ---------------- device scratch (no allocations allowed) ----------------
__device__ float         g_dist[(size_t)NPTS * NPTS];  // 256 MB distance matrix
__device__ float         g_sq[NPTS];
__device__ unsigned char g_lab[NPTS];
__device__ float         g_loss[NPTS];
__device__ float         g_accv[NPTS];
__device__ float         g_tpv[NPTS];
__device__ float         g_tnv[NPTS];
__device__ int           g_is32;

// ---------------- packed fp32x2 helpers (Blackwell FFMA2 path) -----------
__device__ __forceinline__ void fma2(unsigned long long& d,
                                     unsigned long long a,
                                     unsigned long long b) {
    asm("fma.rn.f32x2 %0, %1, %2, %0;" : "+l"(d) : "l"(a), "l"(b));
}
__device__ __forceinline__ unsigned long long pack2(float lo, float hi) {
    unsigned long long r;
    asm("mov.b64 %0, {%1, %2};" : "=l"(r) : "r"(__float_as_uint(lo)), "r"(__float_as_uint(hi)));
    return r;
}
__device__ __forceinline__ void unpack2(unsigned long long v, float& lo, float& hi) {
    unsigned a, b;
    asm("mov.b64 {%0, %1}, %2;" : "=r"(a), "=r"(b) : "l"(v));
    lo = __uint_as_float(a);
    hi = __uint_as_float(b);
}

// ---------------- dtype detection for targets (int32 vs int64) -----------
__global__ void detect_kernel(const int* __restrict__ t) {
    int local = 0;
    for (int j = threadIdx.x; j < 4096; j += blockDim.x) local |= t[2 * j + 1];
#pragma unroll
    for (int off = 16; off; off >>= 1) local |= __shfl_down_sync(0xffffffffu, local, off);
    __shared__ int s[8];
    if ((threadIdx.x & 31) == 0) s[threadIdx.x >> 5] = local;
    __syncthreads();
    if (threadIdx.x == 0) {
        int f = 0;
        for (int w = 0; w < 8; w++) f |= s[w];
        g_is32 = (f != 0);
    }
}

__global__ void conv_kernel(const void* __restrict__ t) {
    int is32 = g_is32;
    int i = blockIdx.x * blockDim.x + threadIdx.x;
    if (i < NPTS) {
        int v = is32 ? ((const int*)t)[i] : (int)(((const long long*)t)[i]);
        g_lab[i] = (unsigned char)v;
    }
}

// ---------------- squared norms ----------------
__global__ void sq_kernel(const float* __restrict__ X) {
    int i = blockIdx.x;
    int tid = threadIdx.x;  // 128 threads
    float v = X[i * DIM + tid];
    v *= v;
#pragma unroll
    for (int off = 16; off; off >>= 1) v += __shfl_down_sync(0xffffffffu, v, off);
    __shared__ float s[4];
    if ((tid & 31) == 0) s[tid >> 5] = v;
    __syncthreads();
    if (tid == 0) g_sq[i] = s[0] + s[1] + s[2] + s[3];
}

// ---------------- distance matrix: symmetric tiled fp32x2 "GEMM" ----------
__global__ void __launch_bounds__(256) dist_kernel(const float* __restrict__ X) {
    __shared__ float As[16][128];
    __shared__ float Bs[16][128];

    const int t = blockIdx.x;
    int b = (int)((sqrtf(8.0f * (float)t + 1.0f) - 1.0f) * 0.5f);
    while ((b * (b + 1)) / 2 > t) b--;
    while (((b + 1) * (b + 2)) / 2 <= t) b++;
    const int by = t - (b * (b + 1)) / 2;   // row tile
    const int bx = b;                       // col tile (>= by)

    const int tid = threadIdx.x;
    const int tx = tid & 15;
    const int ty = tid >> 4;
    const int rowbase = by * 128;
    const int colbase = bx * 128;

    unsigned long long acc2[8][4];
#pragma unroll
    for (int a = 0; a < 8; a++)
#pragma unroll
        for (int c = 0; c < 4; c++) acc2[a][c] = 0ull;

    for (int k0 = 0; k0 < DIM; k0 += 16) {
#pragma unroll
        for (int r = 0; r < 2; r++) {
            int pos = tid + r * 256;
            int row = pos >> 2;
            int kc  = pos & 3;
            float4 va = *(const float4*)&X[(size_t)(rowbase + row) * DIM + k0 + kc * 4];
            As[kc * 4 + 0][row] = va.x;
            As[kc * 4 + 1][row] = va.y;
            As[kc * 4 + 2][row] = va.z;
            As[kc * 4 + 3][row] = va.w;
            float4 vb = *(const float4*)&X[(size_t)(colbase + row) * DIM + k0 + kc * 4];
            Bs[kc * 4 + 0][row] = vb.x;
            Bs[kc * 4 + 1][row] = vb.y;
            Bs[kc * 4 + 2][row] = vb.z;
            Bs[kc * 4 + 3][row] = vb.w;
        }
        __syncthreads();
#pragma unroll
        for (int kk = 0; kk < 16; kk++) {
            float ar[8], br[8];
            *(float4*)&ar[0] = *(const float4*)&As[kk][ty * 8];
            *(float4*)&ar[4] = *(const float4*)&As[kk][ty * 8 + 4];
            *(float4*)&br[0] = *(const float4*)&Bs[kk][tx * 8];
            *(float4*)&br[4] = *(const float4*)&Bs[kk][tx * 8 + 4];
            unsigned long long b2[4];
#pragma unroll
            for (int c = 0; c < 4; c++) b2[c] = pack2(br[2 * c], br[2 * c + 1]);
#pragma unroll
            for (int a = 0; a < 8; a++) {
                unsigned long long a2 = pack2(ar[a], ar[a]);
#pragma unroll
                for (int c = 0; c < 4; c++) fma2(acc2[a][c], a2, b2[c]);
            }
        }
        __syncthreads();
    }

    float sqa[8], sqb[8];
#pragma unroll
    for (int a = 0; a < 8; a++) sqa[a] = g_sq[rowbase + ty * 8 + a];
#pragma unroll
    for (int c = 0; c < 8; c++) sqb[c] = g_sq[colbase + tx * 8 + c];

    float acc[8][8];
#pragma unroll
    for (int a = 0; a < 8; a++)
#pragma unroll
        for (int c = 0; c < 4; c++) {
            float lo, hi;
            unpack2(acc2[a][c], lo, hi);
            acc[a][2 * c]     = sqrtf(fmaxf(sqa[a] + sqb[2 * c]     - 2.0f * lo, 1e-12f));
            acc[a][2 * c + 1] = sqrtf(fmaxf(sqa[a] + sqb[2 * c + 1] - 2.0f * hi, 1e-12f));
        }

#pragma unroll
    for (int a = 0; a < 8; a++) {
        int row = rowbase + ty * 8 + a;
        float4 o0 = make_float4(acc[a][0], acc[a][1], acc[a][2], acc[a][3]);
        float4 o1 = make_float4(acc[a][4], acc[a][5], acc[a][6], acc[a][7]);
        *(float4*)&g_dist[(size_t)row * NPTS + colbase + tx * 8]     = o0;
        *(float4*)&g_dist[(size_t)row * NPTS + colbase + tx * 8 + 4] = o1;
    }

    if (bx != by) {
#pragma unroll
        for (int c = 0; c < 8; c++) {
            int col = colbase + tx * 8 + c;
            float4 p0 = make_float4(acc[0][c], acc[1][c], acc[2][c], acc[3][c]);
            float4 p1 = make_float4(acc[4][c], acc[5][c], acc[6][c], acc[7][c]);
            *(float4*)&g_dist[(size_t)col * NPTS + rowbase + ty * 8]     = p0;
            *(float4*)&g_dist[(size_t)col * NPTS + rowbase + ty * 8 + 4] = p1;
        }
    }
}

// ---------------- per-row kernel: pivot + gather + exact small-select ------
// Row lives in registers (32 floats/thread). Pivot = 17th smallest of the 256
// per-thread minima, a provable upper bound on the true 17th-smallest value,
// so the gathered candidate set (v <= pivot) always contains the answer.
__global__ void __launch_bounds__(256) row_kernel() {
    const int i = blockIdx.x;
    const int tid = threadIdx.x;
    const int lane = tid & 31;
    const int wid = tid >> 5;
    const float INF = __int_as_float(0x7f800000);

    __shared__ float smin[256];
    __shared__ int   swarr[8];
    __shared__ float cand_v[CAND_MAX];
    __shared__ int   cand_j[CAND_MAX];
    __shared__ int   s_cnt;
    __shared__ float s_pivot;
    __shared__ float s_thr;
    __shared__ float sps[8], sns[8], sfpd[8];
    __shared__ int   scp[8], scn[8], sfp[8], san[8];

    // ---- load row into registers: v[c*4+k] = row[c*1024 + 4*tid + k] ----
    float v[32];
    const float4* drow4 = (const float4*)(g_dist + (size_t)i * NPTS);
#pragma unroll
    for (int c = 0; c < 8; c++) {
        float4 t4 = drow4[c * 256 + tid];
        v[c * 4 + 0] = t4.x;
        v[c * 4 + 1] = t4.y;
        v[c * 4 + 2] = t4.z;
        v[c * 4 + 3] = t4.w;
    }
    // diagonal -> +inf (owned by thread (i&1023)>>2, slot (i>>10)*4 + (i&3))
    if (tid == ((i & 1023) >> 2))
        v[((i >> 10) << 2) + (i & 3)] = INF;

    // ---- per-thread min, then pivot = 17th smallest of the 256 mins ----
    float mn = v[0];
#pragma unroll
    for (int c = 1; c < 32; c++) mn = fminf(mn, v[c]);
    smin[tid] = mn;
    if (tid == 0) s_cnt = 0;
    __syncthreads();
    {
        int r = 0;
        for (int s = 0; s < 256; s++) {
            float o = smin[s];
            r += (o < mn) || (o == mn && s < tid);
        }
        if (r == 16) s_pivot = mn;  // unique winner by (value, tid) order
    }
    __syncthreads();
    const float pivot = s_pivot;

    // ---- gather candidates (v <= pivot); shfl uses the ballot mask m ----
#pragma unroll
    for (int c = 0; c < 8; c++) {
#pragma unroll
        for (int k = 0; k < 4; k++) {
            float val = v[c * 4 + k];
            bool sel = (val <= pivot);
            unsigned m = __ballot_sync(0xffffffffu, sel);
            if (sel) {
                int leader = __ffs(m) - 1;
                int base = 0;
                if (lane == leader) base = atomicAdd(&s_cnt, __popc(m));
                base = __shfl_sync(m, base, leader);   // mask = participating lanes
                int pos = base + __popc(m & ((1u << lane) - 1));
                if (pos < CAND_MAX) {
                    cand_v[pos] = val;
                    cand_j[pos] = c * 1024 + 4 * tid + k;
                }
            }
        }
    }
    __syncthreads();
    const int cnt = s_cnt;

    if (cnt <= CAND_MAX) {
        // exact 17th smallest among candidates by (value, index) rank
        for (int t = tid; t < cnt; t += 256) {
            float mv = cand_v[t];
            int mj = cand_j[t];
            int r = 0;
            for (int s = 0; s < cnt; s++) {
                float ov = cand_v[s];
                r += (ov < mv) || (ov == mv && cand_j[s] < mj);
            }
            if (r == 16) s_thr = mv;  // unique by (value, j)
        }
    } else {
        // unconditional-correctness fallback: exact bitwise select (rare)
        unsigned cur = 0;
        int rank = 17;
        for (int bit = 30; bit >= 0; bit--) {
            unsigned mid = cur | (1u << bit);
            int c0 = 0;
#pragma unroll
            for (int c = 0; c < 32; c++) {
                unsigned bits = __float_as_uint(v[c]);
                c0 += (bits >= cur && bits < mid) ? 1 : 0;
            }
            c0 = __reduce_add_sync(0xffffffffu, c0);
            if (lane == 0) swarr[wid] = c0;
            __syncthreads();
            int tot = 0;
            for (int w = 0; w < 8; w++) tot += swarr[w];
            if (tot < rank) { rank -= tot; cur = mid; }
            __syncthreads();
        }
        if (tid == 0) s_thr = __uint_as_float(cur);
    }
    __syncthreads();
    const float thr = s_thr;
    const int myl = g_lab[i];

    // ---- masked sums from registers (strict dist < thr) ----
    float ps = 0.0f, ns = 0.0f, fpd = 0.0f;
    int cp = 0, cn = 0, fp = NPTS, anyneg = 0;
#pragma unroll
    for (int c = 0; c < 8; c++) {
        uchar4 l4 = *(const uchar4*)&g_lab[c * 1024 + 4 * tid];
        unsigned char ll[4] = {l4.x, l4.y, l4.z, l4.w};
#pragma unroll
        for (int k = 0; k < 4; k++) {
            int j = c * 1024 + 4 * tid + k;
            if (j == i) continue;
            float dv = v[c * 4 + k];
            bool below = dv < thr;
            if (ll[k] == myl) {
                if (j < fp) { fp = j; fpd = dv; }
                if (below) { ps += expf(-dv); cp++; }
            } else {
                anyneg = 1;
                if (below) { ns += expf(-dv); cn++; }
            }
        }
    }
#pragma unroll
    for (int off = 16; off; off >>= 1) {
        ps += __shfl_down_sync(0xffffffffu, ps, off);
        ns += __shfl_down_sync(0xffffffffu, ns, off);
        cp += __shfl_down_sync(0xffffffffu, cp, off);
        cn += __shfl_down_sync(0xffffffffu, cn, off);
        int ofp = __shfl_down_sync(0xffffffffu, fp, off);
        float ofpd = __shfl_down_sync(0xffffffffu, fpd, off);
        if (ofp < fp) { fp = ofp; fpd = ofpd; }
        anyneg |= __shfl_down_sync(0xffffffffu, anyneg, off);
    }
    if (lane == 0) {
        sps[wid] = ps; sns[wid] = ns; scp[wid] = cp; scn[wid] = cn;
        sfp[wid] = fp; sfpd[wid] = fpd; san[wid] = anyneg;
    }
    __syncthreads();
    if (tid == 0) {
        ps = 0; ns = 0; cp = 0; cn = 0; fp = NPTS; fpd = 0; anyneg = 0;
        for (int w = 0; w < 8; w++) {
            ps += sps[w]; ns += sns[w]; cp += scp[w]; cn += scn[w];
            if (sfp[w] < fp) { fp = sfp[w]; fpd = sfpd[w]; }
            anyneg |= san[w];
        }
        bool haspos = (fp < NPTS);
        bool validr = haspos && (anyneg != 0);
        float pos_eff = (cp == 0) ? (haspos ? expf(-fpd) : 1.0f) : ps;
        float loss_i = validr ? logf((pos_eff + ns) / pos_eff) : 0.0f;
        int cpa = (cp == 0) ? 1 : cp;
        g_loss[i] = loss_i;
        g_accv[i] = (validr && cpa > cn) ? 1.0f : 0.0f;
        g_tpv[i]  = validr ? (float)cp : 0.0f;
        g_tnv[i]  = validr ? (float)cn : 0.0f;
    }
}

// ---------------- deterministic final reduction ----------------
__global__ void finalize_kernel(float* __restrict__ out) {
    __shared__ float s0[256], s1[256], s2[256], s3[256];
    int tid = threadIdx.x;
    float a = 0, b = 0, c = 0, d = 0;
    for (int j = tid; j < NPTS; j += 256) {
        a += g_loss[j]; b += g_accv[j]; c += g_tpv[j]; d += g_tnv[j];
    }
    s0[tid] = a; s1[tid] = b; s2[tid] = c; s3[tid] = d;
    __syncthreads();
    for (int off = 128; off; off >>= 1) {
        if (tid < off) {
            s0[tid] += s0[tid + off];
            s1[tid] += s1[tid + off];
            s2[tid] += s2[tid + off];
            s3[tid] += s3[tid + off];
        }
        __syncthreads();
    }
    if (tid == 0) {
        const float inv = 1.0f / (float)NPTS;
        out[0] = s0[0] * inv;  // loss
        out[1] = s1[0] * inv;  // accuracy
        out[2] = s2[0] * inv;  // tp
        out[3] = s3[0] * inv;  // tn
    }
}

extern "C" void kernel_launch(void* const* d_in, const int* in_sizes, int n_in,
                              void* d_out, int out_size) {
    const float* X = (const float*)d_in[0];
    const void* T = d_in[1];
    float* out = (float*)d_out;
    (void)in_sizes; (void)n_in; (void)out_size;

    detect_kernel<<<1, 256>>>((const int*)T);
    conv_kernel<<<(NPTS + 255) / 256, 256>>>(T);
    sq_kernel<<<NPTS, 128>>>(X);
    const int ntiles = (NPTS / 128) * (NPTS / 128 + 1) / 2;  // 2080 triangular tiles
    dist_kernel<<<ntiles, 256>>>(X);
    row_kernel<<<NPTS, 256>>>();
    finalize_kernel<<<1, 256>>>(out);
}